// round 1
// baseline (speedup 1.0000x reference)
#include <cuda_runtime.h>
#include <cuda_bf16.h>
#include <math.h>

#define BATCH 16
#define SEQ   512
#define EMB   768
#define HEADS 12
#define HDIM  64
#define ROWS  (BATCH*SEQ)          // 8192

// Scratch for Q/K/V in (B*H, S, D) layout (fp32). 3 x 24 MB.
__device__ float g_Q[BATCH*HEADS*SEQ*HDIM];
__device__ float g_K[BATCH*HEADS*SEQ*HDIM];
__device__ float g_V[BATCH*HEADS*SEQ*HDIM];

// ---------------------------------------------------------------------------
// Kernel 1: fused QKV projection.
// C[m][n] = sum_e inp[m][e] * W[e][n] + bias[n]
// grid: (12 n-tiles, 128 m-tiles, 3 matrices), block 256 (16x16), 4x4 microtile.
// Output written in (B*H, S, D) layout.
// ---------------------------------------------------------------------------
__global__ __launch_bounds__(256) void qkv_proj(
    const float* __restrict__ inp,
    const float* __restrict__ Wq, const float* __restrict__ bq,
    const float* __restrict__ Wk, const float* __restrict__ bk,
    const float* __restrict__ Wv, const float* __restrict__ bv)
{
    const float* W; const float* bias; float* out;
    if (blockIdx.z == 0)      { W = Wq; bias = bq; out = g_Q; }
    else if (blockIdx.z == 1) { W = Wk; bias = bk; out = g_K; }
    else                      { W = Wv; bias = bv; out = g_V; }

    const int m0 = blockIdx.y * 64;
    const int n0 = blockIdx.x * 64;
    const int tid = threadIdx.x;
    const int tx = tid & 15;
    const int ty = tid >> 4;

    __shared__ float As[64][17];   // [m][k] pad 17
    __shared__ float Bs[16][64];   // [k][n]

    float acc[4][4];
    #pragma unroll
    for (int i = 0; i < 4; i++)
        #pragma unroll
        for (int j = 0; j < 4; j++) acc[i][j] = 0.0f;

    for (int k0 = 0; k0 < EMB; k0 += 16) {
        // Load A tile: 64 rows x 16 k. 256 float4 loads.
        {
            int e = tid;                 // 0..255 -> 64x4 float4 slots
            int row = e >> 2;            // 0..63
            int c4  = e & 3;             // 0..3 -> k offset c4*4
            float4 v = *reinterpret_cast<const float4*>(
                &inp[(m0 + row) * EMB + k0 + c4 * 4]);
            As[row][c4*4 + 0] = v.x;
            As[row][c4*4 + 1] = v.y;
            As[row][c4*4 + 2] = v.z;
            As[row][c4*4 + 3] = v.w;
        }
        // Load B tile: 16 k x 64 n. 256 float4 loads.
        {
            int e = tid;
            int row = e >> 4;            // 0..15
            int c4  = e & 15;            // 0..15 -> n offset c4*4
            float4 v = *reinterpret_cast<const float4*>(
                &W[(k0 + row) * EMB + n0 + c4 * 4]);
            *reinterpret_cast<float4*>(&Bs[row][c4*4]) = v;
        }
        __syncthreads();

        #pragma unroll
        for (int kk = 0; kk < 16; kk++) {
            float a[4], b[4];
            #pragma unroll
            for (int i = 0; i < 4; i++) a[i] = As[ty + 16*i][kk];
            #pragma unroll
            for (int j = 0; j < 4; j++) b[j] = Bs[kk][tx + 16*j];
            #pragma unroll
            for (int i = 0; i < 4; i++)
                #pragma unroll
                for (int j = 0; j < 4; j++)
                    acc[i][j] = fmaf(a[i], b[j], acc[i][j]);
        }
        __syncthreads();
    }

    // Epilogue: add bias, store in (B*H, S, D) layout.
    const int h = n0 >> 6;   // head (tiles are head-aligned: 64-wide)
    #pragma unroll
    for (int j = 0; j < 4; j++) {
        const int n = n0 + tx + 16*j;
        const int d = n & 63;
        const float bv_ = bias[n];
        #pragma unroll
        for (int i = 0; i < 4; i++) {
            const int m = m0 + ty + 16*i;
            const int b = m >> 9;
            const int s = m & 511;
            out[((b*HEADS + h)*SEQ + s)*HDIM + d] = acc[i][j] + bv_;
        }
    }
}

// ---------------------------------------------------------------------------
// Kernel 2: attention for one (b, h, 64-query tile).
// Full 64x512 score matrix kept in dynamic smem (pitch 516 for bank spread).
// ---------------------------------------------------------------------------
#define SPITCH 516
#define ATTN_SMEM ((64*SPITCH + 2*64*65) * sizeof(float))

__global__ __launch_bounds__(256) void attn_kernel(
    const float* __restrict__ mask, float* __restrict__ out)
{
    const int b  = blockIdx.z;
    const int h  = blockIdx.y;
    const int q0 = blockIdx.x * 64;
    const int tid = threadIdx.x;
    const int tx = tid & 15;
    const int ty = tid >> 4;

    const float* Qp = g_Q + ((b*HEADS + h)*SEQ + q0)*HDIM;
    const float* Kp = g_K + ((b*HEADS + h)*SEQ)*HDIM;
    const float* Vp = g_V + ((b*HEADS + h)*SEQ)*HDIM;

    extern __shared__ float smem[];
    float* scores = smem;                    // 64 x SPITCH
    float* Qs     = smem + 64*SPITCH;        // 64 x 65
    float* KVs    = Qs   + 64*65;            // 64 x 65
    __shared__ float mb[SEQ];

    // Load Q tile (64x64) into smem, padded pitch 65.
    for (int e = tid; e < 64*16; e += 256) {
        int row = e >> 4;
        int c4  = e & 15;
        float4 v = *reinterpret_cast<const float4*>(&Qp[row*HDIM + c4*4]);
        Qs[row*65 + c4*4 + 0] = v.x;
        Qs[row*65 + c4*4 + 1] = v.y;
        Qs[row*65 + c4*4 + 2] = v.z;
        Qs[row*65 + c4*4 + 3] = v.w;
    }
    // Mask bias over keys.
    for (int i = tid; i < SEQ; i += 256)
        mb[i] = mask[b*SEQ + i] * -1e9f;
    __syncthreads();

    const float scale = 0.125f; // 1/sqrt(64)

    // Phase 1: scores = Q K^T * scale + mask_bias
    for (int kc = 0; kc < SEQ/64; kc++) {
        for (int e = tid; e < 64*16; e += 256) {
            int row = e >> 4;
            int c4  = e & 15;
            float4 v = *reinterpret_cast<const float4*>(
                &Kp[(kc*64 + row)*HDIM + c4*4]);
            KVs[row*65 + c4*4 + 0] = v.x;
            KVs[row*65 + c4*4 + 1] = v.y;
            KVs[row*65 + c4*4 + 2] = v.z;
            KVs[row*65 + c4*4 + 3] = v.w;
        }
        __syncthreads();

        float acc[4][4];
        #pragma unroll
        for (int i = 0; i < 4; i++)
            #pragma unroll
            for (int j = 0; j < 4; j++) acc[i][j] = 0.0f;

        #pragma unroll 8
        for (int kk = 0; kk < 64; kk++) {
            float a[4], c[4];
            #pragma unroll
            for (int i = 0; i < 4; i++) a[i] = Qs[(ty + 16*i)*65 + kk];
            #pragma unroll
            for (int j = 0; j < 4; j++) c[j] = KVs[(tx + 16*j)*65 + kk];
            #pragma unroll
            for (int i = 0; i < 4; i++)
                #pragma unroll
                for (int j = 0; j < 4; j++)
                    acc[i][j] = fmaf(a[i], c[j], acc[i][j]);
        }

        #pragma unroll
        for (int i = 0; i < 4; i++)
            #pragma unroll
            for (int j = 0; j < 4; j++) {
                const int k = kc*64 + tx + 16*j;
                scores[(ty + 16*i)*SPITCH + k] = acc[i][j]*scale + mb[k];
            }
        __syncthreads();
    }

    // Phase 2: row softmax (one thread per query row).
    if (tid < 64) {
        float* row = scores + tid*SPITCH;
        float mx = -INFINITY;
        for (int k = 0; k < SEQ; k++) mx = fmaxf(mx, row[k]);
        float sum = 0.0f;
        for (int k = 0; k < SEQ; k++) {
            float e = __expf(row[k] - mx);
            row[k] = e;
            sum += e;
        }
        float inv = 1.0f / sum;
        for (int k = 0; k < SEQ; k++) row[k] *= inv;
    }
    __syncthreads();

    // Phase 3: O = P V
    float o[4][4];
    #pragma unroll
    for (int i = 0; i < 4; i++)
        #pragma unroll
        for (int j = 0; j < 4; j++) o[i][j] = 0.0f;

    for (int kc = 0; kc < SEQ/64; kc++) {
        for (int e = tid; e < 64*16; e += 256) {
            int row = e >> 4;
            int c4  = e & 15;
            float4 v = *reinterpret_cast<const float4*>(
                &Vp[(kc*64 + row)*HDIM + c4*4]);
            KVs[row*65 + c4*4 + 0] = v.x;
            KVs[row*65 + c4*4 + 1] = v.y;
            KVs[row*65 + c4*4 + 2] = v.z;
            KVs[row*65 + c4*4 + 3] = v.w;
        }
        __syncthreads();

        #pragma unroll 8
        for (int kk = 0; kk < 64; kk++) {
            float w[4], v[4];
            #pragma unroll
            for (int i = 0; i < 4; i++)
                w[i] = scores[(ty + 16*i)*SPITCH + kc*64 + kk];
            #pragma unroll
            for (int j = 0; j < 4; j++) v[j] = KVs[kk*65 + tx + 16*j];
            #pragma unroll
            for (int i = 0; i < 4; i++)
                #pragma unroll
                for (int j = 0; j < 4; j++)
                    o[i][j] = fmaf(w[i], v[j], o[i][j]);
        }
        __syncthreads();
    }

    // Write out: (B, S, H*D)
    #pragma unroll
    for (int i = 0; i < 4; i++) {
        const int q = q0 + ty + 16*i;
        #pragma unroll
        for (int j = 0; j < 4; j++) {
            const int d = tx + 16*j;
            out[(b*SEQ + q)*EMB + h*HDIM + d] = o[i][j];
        }
    }
}

// ---------------------------------------------------------------------------
extern "C" void kernel_launch(void* const* d_in, const int* in_sizes, int n_in,
                              void* d_out, int out_size)
{
    const float* inp  = (const float*)d_in[0];
    const float* mask = (const float*)d_in[1];
    const float* Wq   = (const float*)d_in[2];
    const float* bq   = (const float*)d_in[3];
    const float* Wk   = (const float*)d_in[4];
    const float* bk   = (const float*)d_in[5];
    const float* Wv   = (const float*)d_in[6];
    const float* bv   = (const float*)d_in[7];
    float* out = (float*)d_out;

    cudaFuncSetAttribute(attn_kernel,
                         cudaFuncAttributeMaxDynamicSharedMemorySize,
                         (int)ATTN_SMEM);

    dim3 gproj(EMB/64, ROWS/64, 3);
    qkv_proj<<<gproj, 256>>>(inp, Wq, bq, Wk, bk, Wv, bv);

    dim3 gattn(SEQ/64, HEADS, BATCH);
    attn_kernel<<<gattn, 256, ATTN_SMEM>>>(mask, out);
}

// round 2
// speedup vs baseline: 3.2715x; 3.2715x over previous
#include <cuda_runtime.h>
#include <math.h>

#define BATCH 16
#define SEQ   512
#define EMB   768
#define HEADS 12
#define HDIM  64
#define ROWS  (BATCH*SEQ)          // 8192

// Scratch for Q/K/V in (B*H, S, D) layout (fp32).
__device__ float g_Q[BATCH*HEADS*SEQ*HDIM];
__device__ float g_K[BATCH*HEADS*SEQ*HDIM];
__device__ float g_V[BATCH*HEADS*SEQ*HDIM];

// ---------------------------------------------------------------------------
// TF32 helpers
// ---------------------------------------------------------------------------
__device__ __forceinline__ float tf32r(float x) {
    unsigned u;
    asm("cvt.rna.tf32.f32 %0, %1;" : "=r"(u) : "f"(x));
    return __uint_as_float(u);
}

// mma.sync m16n8k8, A row-major, B col-major, fp32 accumulate.
__device__ __forceinline__ void mma8(float c[4],
                                     float a0, float a1, float a2, float a3,
                                     float b0, float b1) {
    asm volatile(
        "mma.sync.aligned.m16n8k8.row.col.f32.tf32.tf32.f32 "
        "{%0,%1,%2,%3}, {%4,%5,%6,%7}, {%8,%9}, {%0,%1,%2,%3};"
        : "+f"(c[0]), "+f"(c[1]), "+f"(c[2]), "+f"(c[3])
        : "r"(__float_as_uint(a0)), "r"(__float_as_uint(a1)),
          "r"(__float_as_uint(a2)), "r"(__float_as_uint(a3)),
          "r"(__float_as_uint(b0)), "r"(__float_as_uint(b1)));
}

// ---------------------------------------------------------------------------
// Kernel 1: fused QKV projection, TF32 tensor-core GEMM.
// C[m][n] = sum_e inp[m][e]*W[e][n] + bias[n], written to (B*H, S, D).
// Block tile 128x128, 8 warps (2M x 4N) of 64x32, K-step 32.
// ---------------------------------------------------------------------------
#define ASTR 36    // A smem row stride: (36%32)=4 -> 4*row+col conflict-free
#define BSTR 136   // B smem row stride: (136%32)=8 -> 8*k+n conflict-free

__global__ __launch_bounds__(256) void qkv_proj(
    const float* __restrict__ inp,
    const float* __restrict__ Wq, const float* __restrict__ bq,
    const float* __restrict__ Wk, const float* __restrict__ bk,
    const float* __restrict__ Wv, const float* __restrict__ bv)
{
    const float* W; const float* bias; float* out;
    if (blockIdx.z == 0)      { W = Wq; bias = bq; out = g_Q; }
    else if (blockIdx.z == 1) { W = Wk; bias = bk; out = g_K; }
    else                      { W = Wv; bias = bv; out = g_V; }

    const int m0 = blockIdx.y * 128;
    const int n0 = blockIdx.x * 128;
    const int tid  = threadIdx.x;
    const int lane = tid & 31;
    const int wid  = tid >> 5;
    const int wm = (wid & 1) * 64;      // warp M offset
    const int wn = (wid >> 1) * 32;     // warp N offset
    const int g  = lane >> 2;           // group id (0..7)
    const int t  = lane & 3;            // thread-in-group (0..3)

    __shared__ float As[128 * ASTR];    // 18 KB
    __shared__ float Bs[32 * BSTR];     // 17 KB

    float acc[4][4][4];
    #pragma unroll
    for (int mi = 0; mi < 4; mi++)
        #pragma unroll
        for (int nj = 0; nj < 4; nj++)
            #pragma unroll
            for (int c = 0; c < 4; c++) acc[mi][nj][c] = 0.0f;

    for (int k0 = 0; k0 < EMB; k0 += 32) {
        // Stage A: 128 rows x 32 k (tf32-rounded)
        #pragma unroll
        for (int i = 0; i < 4; i++) {
            int f  = tid + i * 256;         // 0..1023
            int r  = f >> 3;
            int c4 = (f & 7) * 4;
            float4 v = *reinterpret_cast<const float4*>(
                &inp[(m0 + r) * EMB + k0 + c4]);
            As[r*ASTR + c4 + 0] = tf32r(v.x);
            As[r*ASTR + c4 + 1] = tf32r(v.y);
            As[r*ASTR + c4 + 2] = tf32r(v.z);
            As[r*ASTR + c4 + 3] = tf32r(v.w);
        }
        // Stage B: 32 k x 128 n (tf32-rounded)
        #pragma unroll
        for (int i = 0; i < 4; i++) {
            int f  = tid + i * 256;
            int r  = f >> 5;
            int c4 = (f & 31) * 4;
            float4 v = *reinterpret_cast<const float4*>(
                &W[(k0 + r) * EMB + n0 + c4]);
            Bs[r*BSTR + c4 + 0] = tf32r(v.x);
            Bs[r*BSTR + c4 + 1] = tf32r(v.y);
            Bs[r*BSTR + c4 + 2] = tf32r(v.z);
            Bs[r*BSTR + c4 + 3] = tf32r(v.w);
        }
        __syncthreads();

        #pragma unroll
        for (int k8 = 0; k8 < 4; k8++) {
            const int kk = k8 * 8;
            float a[4][4], b[4][2];
            #pragma unroll
            for (int mi = 0; mi < 4; mi++) {
                int r = wm + mi*16 + g;
                a[mi][0] = As[r*ASTR + kk + t];
                a[mi][1] = As[(r+8)*ASTR + kk + t];
                a[mi][2] = As[r*ASTR + kk + t + 4];
                a[mi][3] = As[(r+8)*ASTR + kk + t + 4];
            }
            #pragma unroll
            for (int nj = 0; nj < 4; nj++) {
                int c = wn + nj*8 + g;
                b[nj][0] = Bs[(kk + t)*BSTR + c];
                b[nj][1] = Bs[(kk + t + 4)*BSTR + c];
            }
            #pragma unroll
            for (int mi = 0; mi < 4; mi++)
                #pragma unroll
                for (int nj = 0; nj < 4; nj++)
                    mma8(acc[mi][nj], a[mi][0], a[mi][1], a[mi][2], a[mi][3],
                         b[nj][0], b[nj][1]);
        }
        __syncthreads();
    }

    // Epilogue: bias add, scatter to (B*H, S, D).
    #pragma unroll
    for (int mi = 0; mi < 4; mi++) {
        #pragma unroll
        for (int nj = 0; nj < 4; nj++) {
            #pragma unroll
            for (int c = 0; c < 4; c++) {
                int row = m0 + wm + mi*16 + g + ((c >= 2) ? 8 : 0);
                int n   = n0 + wn + nj*8 + 2*t + (c & 1);
                int h = n >> 6, d = n & 63;
                int b = row >> 9, s = row & 511;
                out[((b*HEADS + h)*SEQ + s)*HDIM + d] = acc[mi][nj][c] + bias[n];
            }
        }
    }
}

// ---------------------------------------------------------------------------
// Kernel 2: attention for one (b, h, 64-query tile), TF32 tensor cores.
// scores (64x512, pitch 516) resident in smem; warp-parallel softmax.
// ---------------------------------------------------------------------------
#define SPITCH 516   // 516%32==4 -> conflict-free A-fragment loads
#define QSTR   68    // 68%32==4  -> Q and K fragment loads conflict-free
#define VSTR   72    // 72%32==8  -> V fragment loads conflict-free
#define ATTN_SMEM ((64*SPITCH + 64*QSTR + 64*VSTR) * sizeof(float))

__global__ __launch_bounds__(256) void attn_kernel(
    const float* __restrict__ mask, float* __restrict__ out)
{
    const int b  = blockIdx.z;
    const int h  = blockIdx.y;
    const int q0 = blockIdx.x * 64;
    const int tid  = threadIdx.x;
    const int lane = tid & 31;
    const int wid  = tid >> 5;
    const int wm = (wid >> 1) * 16;   // warp row offset (4 warps over 64 q)
    const int wn = (wid & 1) * 32;    // warp col offset (2 warps over 64 n)
    const int g  = lane >> 2;
    const int t  = lane & 3;

    const float* Qp = g_Q + ((b*HEADS + h)*SEQ + q0)*HDIM;
    const float* Kp = g_K + ((b*HEADS + h)*SEQ)*HDIM;
    const float* Vp = g_V + ((b*HEADS + h)*SEQ)*HDIM;

    extern __shared__ float smem[];
    float* scores = smem;                    // 64 x SPITCH
    float* Qs     = smem + 64*SPITCH;        // 64 x QSTR
    float* KVs    = Qs   + 64*QSTR;          // 64 x VSTR (K uses stride QSTR area-compatible)
    __shared__ float mb[SEQ];

    // Stage Q (tf32) and mask bias.
    #pragma unroll
    for (int i = 0; i < 4; i++) {
        int f  = tid + i * 256;              // 0..1023
        int r  = f >> 4;
        int c4 = (f & 15) * 4;
        float4 v = *reinterpret_cast<const float4*>(&Qp[r*HDIM + c4]);
        Qs[r*QSTR + c4 + 0] = tf32r(v.x);
        Qs[r*QSTR + c4 + 1] = tf32r(v.y);
        Qs[r*QSTR + c4 + 2] = tf32r(v.z);
        Qs[r*QSTR + c4 + 3] = tf32r(v.w);
    }
    for (int i = tid; i < SEQ; i += 256)
        mb[i] = mask[b*SEQ + i] * -1e9f;
    __syncthreads();

    const float scale = 0.125f;

    // -------- Phase 1: S = Q K^T * scale + mask --------
    for (int kc = 0; kc < SEQ/64; kc++) {
        // Stage K chunk (64 keys x 64 d), stride QSTR.
        #pragma unroll
        for (int i = 0; i < 4; i++) {
            int f  = tid + i * 256;
            int r  = f >> 4;
            int c4 = (f & 15) * 4;
            float4 v = *reinterpret_cast<const float4*>(
                &Kp[(kc*64 + r)*HDIM + c4]);
            KVs[r*QSTR + c4 + 0] = tf32r(v.x);
            KVs[r*QSTR + c4 + 1] = tf32r(v.y);
            KVs[r*QSTR + c4 + 2] = tf32r(v.z);
            KVs[r*QSTR + c4 + 3] = tf32r(v.w);
        }
        __syncthreads();

        float acc[4][4];
        #pragma unroll
        for (int nj = 0; nj < 4; nj++)
            #pragma unroll
            for (int c = 0; c < 4; c++) acc[nj][c] = 0.0f;

        #pragma unroll
        for (int k8 = 0; k8 < 8; k8++) {
            const int kk = k8 * 8;
            int r = wm + g;
            float a0 = Qs[r*QSTR + kk + t];
            float a1 = Qs[(r+8)*QSTR + kk + t];
            float a2 = Qs[r*QSTR + kk + t + 4];
            float a3 = Qs[(r+8)*QSTR + kk + t + 4];
            #pragma unroll
            for (int nj = 0; nj < 4; nj++) {
                int col = wn + nj*8 + g;             // key index in chunk
                float b0 = KVs[col*QSTR + kk + t];
                float b1 = KVs[col*QSTR + kk + t + 4];
                mma8(acc[nj], a0, a1, a2, a3, b0, b1);
            }
        }

        #pragma unroll
        for (int nj = 0; nj < 4; nj++) {
            int key = kc*64 + wn + nj*8 + 2*t;
            int r = wm + g;
            scores[r*SPITCH + key]     = acc[nj][0]*scale + mb[key];
            scores[r*SPITCH + key + 1] = acc[nj][1]*scale + mb[key+1];
            scores[(r+8)*SPITCH + key]     = acc[nj][2]*scale + mb[key];
            scores[(r+8)*SPITCH + key + 1] = acc[nj][3]*scale + mb[key+1];
        }
        __syncthreads();
    }

    // -------- Phase 2: warp-parallel row softmax --------
    for (int r = wid; r < 64; r += 8) {
        float* row = scores + r*SPITCH;
        float mx = -INFINITY;
        for (int k = lane; k < SEQ; k += 32) mx = fmaxf(mx, row[k]);
        #pragma unroll
        for (int off = 16; off > 0; off >>= 1)
            mx = fmaxf(mx, __shfl_xor_sync(0xffffffffu, mx, off));
        float sum = 0.0f;
        for (int k = lane; k < SEQ; k += 32) {
            float e = __expf(row[k] - mx);
            row[k] = e;
            sum += e;
        }
        #pragma unroll
        for (int off = 16; off > 0; off >>= 1)
            sum += __shfl_xor_sync(0xffffffffu, sum, off);
        float inv = 1.0f / sum;
        for (int k = lane; k < SEQ; k += 32)
            row[k] = tf32r(row[k] * inv);
    }
    __syncthreads();

    // -------- Phase 3: O = P V --------
    float o[4][4];
    #pragma unroll
    for (int nj = 0; nj < 4; nj++)
        #pragma unroll
        for (int c = 0; c < 4; c++) o[nj][c] = 0.0f;

    for (int kc = 0; kc < SEQ/64; kc++) {
        // Stage V chunk, stride VSTR.
        #pragma unroll
        for (int i = 0; i < 4; i++) {
            int f  = tid + i * 256;
            int r  = f >> 4;
            int c4 = (f & 15) * 4;
            float4 v = *reinterpret_cast<const float4*>(
                &Vp[(kc*64 + r)*HDIM + c4]);
            KVs[r*VSTR + c4 + 0] = tf32r(v.x);
            KVs[r*VSTR + c4 + 1] = tf32r(v.y);
            KVs[r*VSTR + c4 + 2] = tf32r(v.z);
            KVs[r*VSTR + c4 + 3] = tf32r(v.w);
        }
        __syncthreads();

        #pragma unroll
        for (int k8 = 0; k8 < 8; k8++) {
            const int kk = k8 * 8;
            int r = wm + g;
            int col = kc*64 + kk + t;
            float a0 = scores[r*SPITCH + col];
            float a1 = scores[(r+8)*SPITCH + col];
            float a2 = scores[r*SPITCH + col + 4];
            float a3 = scores[(r+8)*SPITCH + col + 4];
            #pragma unroll
            for (int nj = 0; nj < 4; nj++) {
                int d = wn + nj*8 + g;
                float b0 = KVs[(kk + t)*VSTR + d];
                float b1 = KVs[(kk + t + 4)*VSTR + d];
                mma8(o[nj], a0, a1, a2, a3, b0, b1);
            }
        }
        __syncthreads();
    }

    // Write out: (B, S, H*D)
    #pragma unroll
    for (int nj = 0; nj < 4; nj++) {
        #pragma unroll
        for (int c = 0; c < 4; c++) {
            int q = q0 + wm + g + ((c >= 2) ? 8 : 0);
            int d = wn + nj*8 + 2*t + (c & 1);
            out[(b*SEQ + q)*EMB + h*HDIM + d] = o[nj][c];
        }
    }
}

// ---------------------------------------------------------------------------
extern "C" void kernel_launch(void* const* d_in, const int* in_sizes, int n_in,
                              void* d_out, int out_size)
{
    const float* inp  = (const float*)d_in[0];
    const float* mask = (const float*)d_in[1];
    const float* Wq   = (const float*)d_in[2];
    const float* bq   = (const float*)d_in[3];
    const float* Wk   = (const float*)d_in[4];
    const float* bk   = (const float*)d_in[5];
    const float* Wv   = (const float*)d_in[6];
    const float* bv   = (const float*)d_in[7];
    float* out = (float*)d_out;

    cudaFuncSetAttribute(attn_kernel,
                         cudaFuncAttributeMaxDynamicSharedMemorySize,
                         (int)ATTN_SMEM);

    dim3 gproj(EMB/128, ROWS/128, 3);
    qkv_proj<<<gproj, 256>>>(inp, Wq, bq, Wk, bk, Wv, bv);

    dim3 gattn(SEQ/64, HEADS, BATCH);
    attn_kernel<<<gattn, 256, ATTN_SMEM>>>(mask, out);
}

// round 3
// speedup vs baseline: 5.0845x; 1.5542x over previous
#include <cuda_runtime.h>
#include <math.h>

#define BATCH 16
#define SEQ   512
#define EMB   768
#define HEADS 12
#define HDIM  64
#define ROWS  (BATCH*SEQ)          // 8192

// Scratch for Q/K/V in (B*H, S, D) layout (fp32).
__device__ float g_Q[BATCH*HEADS*SEQ*HDIM];
__device__ float g_K[BATCH*HEADS*SEQ*HDIM];
__device__ float g_V[BATCH*HEADS*SEQ*HDIM];

// ---------------------------------------------------------------------------
// TF32 helpers
// ---------------------------------------------------------------------------
__device__ __forceinline__ float tf32r(float x) {
    unsigned u;
    asm("cvt.rna.tf32.f32 %0, %1;" : "=r"(u) : "f"(x));
    return __uint_as_float(u);
}

__device__ __forceinline__ void mma8(float c[4],
                                     float a0, float a1, float a2, float a3,
                                     float b0, float b1) {
    asm volatile(
        "mma.sync.aligned.m16n8k8.row.col.f32.tf32.tf32.f32 "
        "{%0,%1,%2,%3}, {%4,%5,%6,%7}, {%8,%9}, {%0,%1,%2,%3};"
        : "+f"(c[0]), "+f"(c[1]), "+f"(c[2]), "+f"(c[3])
        : "r"(__float_as_uint(a0)), "r"(__float_as_uint(a1)),
          "r"(__float_as_uint(a2)), "r"(__float_as_uint(a3)),
          "r"(__float_as_uint(b0)), "r"(__float_as_uint(b1)));
}

// ---------------------------------------------------------------------------
// Kernel 1: fused QKV projection, TF32, register-prefetch double buffering.
// Block tile 128x128, 8 warps (2M x 4N) of 64x32, K-step 32.
// ---------------------------------------------------------------------------
#define ASTR 36
#define BSTR 136
#define KITERS (EMB/32)   // 24

__global__ __launch_bounds__(256) void qkv_proj(
    const float* __restrict__ inp,
    const float* __restrict__ Wq, const float* __restrict__ bq,
    const float* __restrict__ Wk, const float* __restrict__ bk,
    const float* __restrict__ Wv, const float* __restrict__ bv)
{
    const float* W; const float* bias; float* out;
    if (blockIdx.z == 0)      { W = Wq; bias = bq; out = g_Q; }
    else if (blockIdx.z == 1) { W = Wk; bias = bk; out = g_K; }
    else                      { W = Wv; bias = bv; out = g_V; }

    const int m0 = blockIdx.y * 128;
    const int n0 = blockIdx.x * 128;
    const int tid  = threadIdx.x;
    const int lane = tid & 31;
    const int wid  = tid >> 5;
    const int wm = (wid & 1) * 64;
    const int wn = (wid >> 1) * 32;
    const int g  = lane >> 2;
    const int t  = lane & 3;

    __shared__ float As[128 * ASTR];
    __shared__ float Bs[32 * BSTR];

    float acc[4][4][4];
    #pragma unroll
    for (int mi = 0; mi < 4; mi++)
        #pragma unroll
        for (int nj = 0; nj < 4; nj++)
            #pragma unroll
            for (int c = 0; c < 4; c++) acc[mi][nj][c] = 0.0f;

    // Per-thread staging coordinates
    const int ar  = tid >> 1;            // A: 128 rows, 2 float4 per row slice
    const int ac4 = (tid & 1) * 16;      // plus i*4 within
    const int br  = tid >> 5;            // B: 32 rows ... recomputed below
    (void)br;

    float4 pa[4], pb[4];

    // A tile: 128 x 32 = 1024 float4 -> 4/thread ; f = tid + i*256
    #define LD_A(K0) { _Pragma("unroll") for (int i = 0; i < 4; i++) { \
        int f = tid + i*256; int r = f >> 3; int c4 = (f & 7) * 4; \
        pa[i] = *reinterpret_cast<const float4*>(&inp[(m0 + r)*EMB + (K0) + c4]); } }
    #define LD_B(K0) { _Pragma("unroll") for (int i = 0; i < 4; i++) { \
        int f = tid + i*256; int r = f >> 5; int c4 = (f & 31) * 4; \
        pb[i] = *reinterpret_cast<const float4*>(&W[((K0) + r)*EMB + n0 + c4]); } }
    #define ST_AB() { _Pragma("unroll") for (int i = 0; i < 4; i++) { \
        int f = tid + i*256; int r = f >> 3; int c4 = (f & 7) * 4; \
        As[r*ASTR + c4 + 0] = tf32r(pa[i].x); As[r*ASTR + c4 + 1] = tf32r(pa[i].y); \
        As[r*ASTR + c4 + 2] = tf32r(pa[i].z); As[r*ASTR + c4 + 3] = tf32r(pa[i].w); \
        int rb = f >> 5; int cb = (f & 31) * 4; \
        Bs[rb*BSTR + cb + 0] = tf32r(pb[i].x); Bs[rb*BSTR + cb + 1] = tf32r(pb[i].y); \
        Bs[rb*BSTR + cb + 2] = tf32r(pb[i].z); Bs[rb*BSTR + cb + 3] = tf32r(pb[i].w); } }

    LD_A(0); LD_B(0);
    ST_AB();
    __syncthreads();

    for (int it = 0; it < KITERS; it++) {
        const bool has_next = (it + 1) < KITERS;
        if (has_next) { LD_A((it+1)*32); LD_B((it+1)*32); }

        #pragma unroll
        for (int k8 = 0; k8 < 4; k8++) {
            const int kk = k8 * 8;
            float a[4][4], b[4][2];
            #pragma unroll
            for (int mi = 0; mi < 4; mi++) {
                int r = wm + mi*16 + g;
                a[mi][0] = As[r*ASTR + kk + t];
                a[mi][1] = As[(r+8)*ASTR + kk + t];
                a[mi][2] = As[r*ASTR + kk + t + 4];
                a[mi][3] = As[(r+8)*ASTR + kk + t + 4];
            }
            #pragma unroll
            for (int nj = 0; nj < 4; nj++) {
                int c = wn + nj*8 + g;
                b[nj][0] = Bs[(kk + t)*BSTR + c];
                b[nj][1] = Bs[(kk + t + 4)*BSTR + c];
            }
            #pragma unroll
            for (int mi = 0; mi < 4; mi++)
                #pragma unroll
                for (int nj = 0; nj < 4; nj++)
                    mma8(acc[mi][nj], a[mi][0], a[mi][1], a[mi][2], a[mi][3],
                         b[nj][0], b[nj][1]);
        }

        if (has_next) {
            __syncthreads();
            ST_AB();
            __syncthreads();
        }
    }

    // Epilogue: bias add, scatter to (B*H, S, D).
    #pragma unroll
    for (int mi = 0; mi < 4; mi++) {
        #pragma unroll
        for (int nj = 0; nj < 4; nj++) {
            #pragma unroll
            for (int c = 0; c < 4; c++) {
                int row = m0 + wm + mi*16 + g + ((c >= 2) ? 8 : 0);
                int n   = n0 + wn + nj*8 + 2*t + (c & 1);
                int h = n >> 6, d = n & 63;
                int b = row >> 9, s = row & 511;
                out[((b*HEADS + h)*SEQ + s)*HDIM + d] = acc[mi][nj][c] + bias[n];
            }
        }
    }
}

// ---------------------------------------------------------------------------
// Kernel 2: flash attention, 128 queries/CTA, online softmax in registers.
// 8 warps x 16 query rows. S and O tiles in registers; P via quad shuffles.
// ---------------------------------------------------------------------------
#define QSTR 68
#define KSTR 68
#define VSTR 72
#define ATTN_SMEM ((128*QSTR + 64*KSTR + 64*VSTR + 512) * sizeof(float))

__global__ __launch_bounds__(256) void attn_kernel(
    const float* __restrict__ mask, float* __restrict__ out)
{
    const int b  = blockIdx.z;
    const int h  = blockIdx.y;
    const int q0 = blockIdx.x * 128;
    const int tid  = threadIdx.x;
    const int lane = tid & 31;
    const int wid  = tid >> 5;
    const int wm = wid * 16;
    const int g  = lane >> 2;
    const int t  = lane & 3;

    const float* Qp = g_Q + ((b*HEADS + h)*SEQ + q0)*HDIM;
    const float* Kp = g_K + ((b*HEADS + h)*SEQ)*HDIM;
    const float* Vp = g_V + ((b*HEADS + h)*SEQ)*HDIM;

    extern __shared__ float smem[];
    float* Qs = smem;                     // 128 x QSTR
    float* Ks = Qs + 128*QSTR;            // 64 x KSTR
    float* Vs = Ks + 64*KSTR;             // 64 x VSTR
    float* mb = Vs + 64*VSTR;             // 512

    // Stage Q (tf32) and mask bias.
    #pragma unroll
    for (int i = 0; i < 8; i++) {
        int f = tid + i*256;              // 0..2047
        int r = f >> 4;
        int c4 = (f & 15) * 4;
        float4 v = *reinterpret_cast<const float4*>(&Qp[r*HDIM + c4]);
        Qs[r*QSTR + c4 + 0] = tf32r(v.x);
        Qs[r*QSTR + c4 + 1] = tf32r(v.y);
        Qs[r*QSTR + c4 + 2] = tf32r(v.z);
        Qs[r*QSTR + c4 + 3] = tf32r(v.w);
    }
    for (int i = tid; i < SEQ; i += 256)
        mb[i] = mask[b*SEQ + i] * -1e9f;

    float oacc[8][4];
    #pragma unroll
    for (int dj = 0; dj < 8; dj++)
        #pragma unroll
        for (int c = 0; c < 4; c++) oacc[dj][c] = 0.0f;
    float m0 = -INFINITY, m1 = -INFINITY, l0 = 0.0f, l1 = 0.0f;
    const float scale = 0.125f;
    const unsigned FULL = 0xffffffffu;

    for (int kc = 0; kc < SEQ/64; kc++) {
        __syncthreads();   // protect Ks/Vs from previous chunk; Qs ready on kc=0
        // Stage K and V chunks (tf32).
        #pragma unroll
        for (int i = 0; i < 4; i++) {
            int f = tid + i*256;
            int r = f >> 4;
            int c4 = (f & 15) * 4;
            float4 kv = *reinterpret_cast<const float4*>(&Kp[(kc*64 + r)*HDIM + c4]);
            Ks[r*KSTR + c4 + 0] = tf32r(kv.x);
            Ks[r*KSTR + c4 + 1] = tf32r(kv.y);
            Ks[r*KSTR + c4 + 2] = tf32r(kv.z);
            Ks[r*KSTR + c4 + 3] = tf32r(kv.w);
            float4 vv = *reinterpret_cast<const float4*>(&Vp[(kc*64 + r)*HDIM + c4]);
            Vs[r*VSTR + c4 + 0] = tf32r(vv.x);
            Vs[r*VSTR + c4 + 1] = tf32r(vv.y);
            Vs[r*VSTR + c4 + 2] = tf32r(vv.z);
            Vs[r*VSTR + c4 + 3] = tf32r(vv.w);
        }
        __syncthreads();

        // ---- S = Q K^T ----
        float sacc[8][4];
        #pragma unroll
        for (int nj = 0; nj < 8; nj++)
            #pragma unroll
            for (int c = 0; c < 4; c++) sacc[nj][c] = 0.0f;

        #pragma unroll
        for (int k8 = 0; k8 < 8; k8++) {
            const int kk = k8 * 8;
            int r = wm + g;
            float a0 = Qs[r*QSTR + kk + t];
            float a1 = Qs[(r+8)*QSTR + kk + t];
            float a2 = Qs[r*QSTR + kk + t + 4];
            float a3 = Qs[(r+8)*QSTR + kk + t + 4];
            #pragma unroll
            for (int nj = 0; nj < 8; nj++) {
                int col = nj*8 + g;
                float b0 = Ks[col*KSTR + kk + t];
                float b1 = Ks[col*KSTR + kk + t + 4];
                mma8(sacc[nj], a0, a1, a2, a3, b0, b1);
            }
        }

        // ---- online softmax (registers) ----
        float mx0 = -INFINITY, mx1 = -INFINITY;
        #pragma unroll
        for (int nj = 0; nj < 8; nj++) {
            int key = kc*64 + nj*8 + 2*t;
            sacc[nj][0] = sacc[nj][0]*scale + mb[key];
            sacc[nj][1] = sacc[nj][1]*scale + mb[key+1];
            sacc[nj][2] = sacc[nj][2]*scale + mb[key];
            sacc[nj][3] = sacc[nj][3]*scale + mb[key+1];
            mx0 = fmaxf(mx0, fmaxf(sacc[nj][0], sacc[nj][1]));
            mx1 = fmaxf(mx1, fmaxf(sacc[nj][2], sacc[nj][3]));
        }
        mx0 = fmaxf(mx0, __shfl_xor_sync(FULL, mx0, 1));
        mx0 = fmaxf(mx0, __shfl_xor_sync(FULL, mx0, 2));
        mx1 = fmaxf(mx1, __shfl_xor_sync(FULL, mx1, 1));
        mx1 = fmaxf(mx1, __shfl_xor_sync(FULL, mx1, 2));

        float mn0 = fmaxf(m0, mx0);
        float mn1 = fmaxf(m1, mx1);
        float al0 = __expf(m0 - mn0);
        float al1 = __expf(m1 - mn1);
        m0 = mn0; m1 = mn1;

        float rs0 = 0.0f, rs1 = 0.0f;
        #pragma unroll
        for (int nj = 0; nj < 8; nj++) {
            float p0 = __expf(sacc[nj][0] - mn0);
            float p1 = __expf(sacc[nj][1] - mn0);
            float p2 = __expf(sacc[nj][2] - mn1);
            float p3 = __expf(sacc[nj][3] - mn1);
            sacc[nj][0] = p0; sacc[nj][1] = p1;
            sacc[nj][2] = p2; sacc[nj][3] = p3;
            rs0 += p0 + p1; rs1 += p2 + p3;
        }
        l0 = l0*al0 + rs0;
        l1 = l1*al1 + rs1;
        #pragma unroll
        for (int dj = 0; dj < 8; dj++) {
            oacc[dj][0] *= al0; oacc[dj][1] *= al0;
            oacc[dj][2] *= al1; oacc[dj][3] *= al1;
        }

        // ---- O += P V : convert C-layout P to A-frags via quad shuffles ----
        const int base = lane & ~3;
        const int s0 = base + (t >> 1);
        const int s1 = s0 + 2;
        #pragma unroll
        for (int nj = 0; nj < 8; nj++) {
            const int kk = nj * 8;
            float c0 = tf32r(sacc[nj][0]);
            float c1 = tf32r(sacc[nj][1]);
            float c2 = tf32r(sacc[nj][2]);
            float c3 = tf32r(sacc[nj][3]);
            float v00 = __shfl_sync(FULL, c0, s0);
            float v01 = __shfl_sync(FULL, c1, s0);
            float v02 = __shfl_sync(FULL, c2, s0);
            float v03 = __shfl_sync(FULL, c3, s0);
            float v10 = __shfl_sync(FULL, c0, s1);
            float v11 = __shfl_sync(FULL, c1, s1);
            float v12 = __shfl_sync(FULL, c2, s1);
            float v13 = __shfl_sync(FULL, c3, s1);
            bool odd = (t & 1);
            float a0 = odd ? v01 : v00;   // P[g][kk+t]
            float a1 = odd ? v03 : v02;   // P[g+8][kk+t]
            float a2 = odd ? v11 : v10;   // P[g][kk+t+4]
            float a3 = odd ? v13 : v12;   // P[g+8][kk+t+4]
            #pragma unroll
            for (int dj = 0; dj < 8; dj++) {
                int d = dj*8 + g;
                float b0 = Vs[(kk + t)*VSTR + d];
                float b1 = Vs[(kk + t + 4)*VSTR + d];
                mma8(oacc[dj], a0, a1, a2, a3, b0, b1);
            }
        }
    }

    // ---- normalize and write out (B, S, H*D) ----
    l0 += __shfl_xor_sync(FULL, l0, 1);
    l0 += __shfl_xor_sync(FULL, l0, 2);
    l1 += __shfl_xor_sync(FULL, l1, 1);
    l1 += __shfl_xor_sync(FULL, l1, 2);
    float inv0 = 1.0f / l0;
    float inv1 = 1.0f / l1;

    const int qa = q0 + wm + g;
    const int qb = qa + 8;
    #pragma unroll
    for (int dj = 0; dj < 8; dj++) {
        int d = h*HDIM + dj*8 + 2*t;
        out[(b*SEQ + qa)*EMB + d]     = oacc[dj][0] * inv0;
        out[(b*SEQ + qa)*EMB + d + 1] = oacc[dj][1] * inv0;
        out[(b*SEQ + qb)*EMB + d]     = oacc[dj][2] * inv1;
        out[(b*SEQ + qb)*EMB + d + 1] = oacc[dj][3] * inv1;
    }
}

// ---------------------------------------------------------------------------
extern "C" void kernel_launch(void* const* d_in, const int* in_sizes, int n_in,
                              void* d_out, int out_size)
{
    const float* inp  = (const float*)d_in[0];
    const float* mask = (const float*)d_in[1];
    const float* Wq   = (const float*)d_in[2];
    const float* bq   = (const float*)d_in[3];
    const float* Wk   = (const float*)d_in[4];
    const float* bk   = (const float*)d_in[5];
    const float* Wv   = (const float*)d_in[6];
    const float* bv   = (const float*)d_in[7];
    float* out = (float*)d_out;

    cudaFuncSetAttribute(attn_kernel,
                         cudaFuncAttributeMaxDynamicSharedMemorySize,
                         (int)ATTN_SMEM);

    dim3 gproj(EMB/128, ROWS/128, 3);
    qkv_proj<<<gproj, 256>>>(inp, Wq, bq, Wk, bk, Wv, bv);

    dim3 gattn(SEQ/128, HEADS, BATCH);
    attn_kernel<<<gattn, 256, ATTN_SMEM>>>(mask, out);
}